// round 13
// baseline (speedup 1.0000x reference)
#include <cuda_runtime.h>
#include <cstdint>

#define HW       64
#define CH       3
#define NPIX     (HW * HW)              // 4096
#define NELEM    (NPIX * CH)            // 12288 floats per image
#define ROWS_C   32                     // output rows per CTA (half image)
#define T_A      256
#define PPT      ((ROWS_C * HW) / T_A)  // 8 pixels per thread
#define SMEM_A   (32 * 4 + ROWS_C * HW * 16)  // scratch + 32-row tile = 32896 B
#define LOG2E    1.4426950408889634f

__device__ __forceinline__ float ex2f(float x) {
    float r; asm("ex2.approx.ftz.f32 %0, %1;" : "=f"(r) : "f"(x)); return r;
}
__device__ __forceinline__ float rcpf(float x) {
    float r; asm("rcp.approx.ftz.f32 %0, %1;" : "=f"(r) : "f"(x)); return r;
}
__device__ __forceinline__ float tanhf_approx(float x) {
    float r; asm("tanh.approx.f32 %0, %1;" : "=f"(r) : "f"(x)); return r;
}
__device__ __forceinline__ unsigned int smem_u32(const void* p) {
    unsigned int a;
    asm("{ .reg .u64 t; cvta.to.shared.u64 t, %1; cvt.u32.u64 %0, t; }"
        : "=r"(a) : "l"(p));
    return a;
}
__device__ __forceinline__ unsigned int mapa_u32(unsigned int a, unsigned int r) {
    unsigned int d;
    asm("mapa.shared::cluster.u32 %0, %1, %2;" : "=r"(d) : "r"(a), "r"(r));
    return d;
}
__device__ __forceinline__ float4 ld4_cluster(unsigned int a) {
    float4 v;
    asm volatile("ld.shared::cluster.v4.f32 {%0,%1,%2,%3}, [%4];"
                 : "=f"(v.x), "=f"(v.y), "=f"(v.z), "=f"(v.w) : "r"(a));
    return v;
}
__device__ __forceinline__ void st_peer_f32(unsigned int laddr, unsigned int peer_rank, float v) {
    unsigned int r;
    asm("mapa.shared::cluster.u32 %0, %1, %2;" : "=r"(r) : "r"(laddr), "r"(peer_rank));
    asm volatile("st.shared::cluster.f32 [%0], %1;" :: "r"(r), "f"(v) : "memory");
}

__global__ void __launch_bounds__(T_A, 7) __cluster_dims__(2, 1, 1)
dns_kernel(const float* __restrict__ images,
           const float* __restrict__ params,
           const float* __restrict__ kptr,
           float* __restrict__ out)
{
    extern __shared__ float smem[];
    // red layout: [0..7] noise warp partials, [8..15] det warp partials,
    //             [16..17] own totals, [18..19] peer totals
    float*  red  = smem;
    float*  buf  = smem + 32;            // ROWS_C*HW float4 (own rows only)
    float4* buf4 = (float4*)buf;

    const int tid = threadIdx.x;
    unsigned int rank;
    asm("mov.u32 %0, %%cluster_ctarank;" : "=r"(rank));

    const int img  = blockIdx.x >> 1;
    const int row0 = (int)rank * ROWS_C;          // first output row of CTA
    const float* base = images + (size_t)img * NELEM;
    float*       dst  = out    + (size_t)img * NELEM;

    // ---- stage own 32 rows: per-pixel gather + norm, one STS.128 ----
    {
        const float* src = base + row0 * (HW * CH);
        #pragma unroll
        for (int it = 0; it < PPT; ++it) {
            const int pp = tid + it * T_A;        // 0..2047 local pixel
            const float* q = src + pp * 3;
            const float vx = q[0], vy = q[1], vz = q[2];
            const float nw = fmaf(vx, vx, fmaf(vy, vy, vz * vz));
            buf4[pp] = make_float4(vx, vy, vz, nw);
        }
    }

    // ---- per-image parameters (uniform; L2-resident) ----
    const float* p = params + img * 7;
    const float sigma_s = fminf(fmaxf(p[0], 0.2f), 5.0f);
    const float sigma_r = fminf(fmaxf(p[1], 0.01f), 1.0f);
    const float sigma_f = fminf(fmaxf(p[2], 0.2f), 3.0f);
    const float lam     = fminf(fmaxf(p[3], 0.1f), 2.0f);
    const float tau     = fminf(fmaxf(p[4], 0.5f), 5.0f);
    const float gain    = fminf(fmaxf(p[5], 0.2f), 2.0f);
    const float offset  = fminf(fmaxf(p[6], 0.01f), 1.0f);
    const float k_pos   = fmaxf(fabsf(*kptr), 1.0f);

    const float ls2      = (-0.5f / (sigma_s * sigma_s)) * LOG2E;
    const float b_edge   = ls2;
    const float b_corner = 2.0f * ls2;
    const float cR       = (-0.5f / (sigma_r * sigma_r)) * LOG2E;
    const float m2       = -2.0f * cR;

    const float ef   = __expf(-0.5f / (sigma_f * sigma_f));
    const float ef2  = ef * ef;
    const float ifn  = rcpf(1.0f + 2.0f * ef);
    const float ifn2 = ifn * ifn;

    const float invtau2L2 = rcpf(tau * tau) * LOG2E;
    const float khalf     = 0.5f * k_pos;

    const unsigned int tile_base = smem_u32(buf);

    // both CTAs' tiles must be staged before cross-CTA halo reads
    __syncthreads();
    asm volatile("barrier.cluster.arrive.aligned;" ::: "memory");
    asm volatile("barrier.cluster.wait.aligned;"   ::: "memory");

    float sum_noise = 0.0f, sum_det = 0.0f;

    #pragma unroll
    for (int i = 0; i < PPT; ++i) {
        const int lp = tid + i * T_A;             // 0..2047 in half-image
        const int ly = lp >> 6, x = lp & 63;      // warp-uniform ly
        const int xm = abs(x - 1);
        const int xp = 63 - abs(62 - x);
        const int rC = ly * HW;

        const float4 C = buf4[rC + x];
        const float a0 = m2 * C.x, a1 = m2 * C.y, a2 = m2 * C.z;
        const float cbE = fmaf(cR, C.w, b_edge);
        const float cbC = fmaf(cR, C.w, b_corner);

        float bn0 = C.x, bn1 = C.y, bn2 = C.z, bden = 1.0f;
        float e40 = 0.f, e41 = 0.f, e42 = 0.f;
        float c40 = 0.f, c41 = 0.f, c42 = 0.f;

        #define TAPV(T, CB, A0, A1, A2)                                    \
        {                                                                  \
            const float4 t = (T);                                          \
            float arg = fmaf(cR, t.w, CB);                                 \
            arg = fmaf(a2, t.z, arg);                                      \
            arg = fmaf(a1, t.y, arg);                                      \
            arg = fmaf(a0, t.x, arg);                                      \
            const float kk = ex2f(arg);                                    \
            bden += kk;                                                    \
            bn0 = fmaf(kk, t.x, bn0);                                      \
            bn1 = fmaf(kk, t.y, bn1);                                      \
            bn2 = fmaf(kk, t.z, bn2);                                      \
            A0 += t.x; A1 += t.y; A2 += t.z;                               \
        }

        // center row (always local)
        TAPV(buf4[rC + xm], cbE, e40, e41, e42)
        TAPV(buf4[rC + xp], cbE, e40, e41, e42)

        // up row: remote only for rank1 at ly==0 (peer's row 31)
        if (!(ly == 0 && rank == 1)) {
            const int r = ((ly > 0) ? ly - 1 : 1) * HW;   // reflect for rank0
            TAPV(buf4[r + x ], cbE, e40, e41, e42)
            TAPV(buf4[r + xm], cbC, c40, c41, c42)
            TAPV(buf4[r + xp], cbC, c40, c41, c42)
        } else {
            const unsigned int b = mapa_u32(tile_base + 31u * (HW * 16), 0u);
            TAPV(ld4_cluster(b + x  * 16), cbE, e40, e41, e42)
            TAPV(ld4_cluster(b + xm * 16), cbC, c40, c41, c42)
            TAPV(ld4_cluster(b + xp * 16), cbC, c40, c41, c42)
        }

        // down row: remote only for rank0 at ly==31 (peer's row 0)
        if (!(ly == 31 && rank == 0)) {
            const int r = ((ly < 31) ? ly + 1 : 30) * HW; // reflect for rank1
            TAPV(buf4[r + x ], cbE, e40, e41, e42)
            TAPV(buf4[r + xm], cbC, c40, c41, c42)
            TAPV(buf4[r + xp], cbC, c40, c41, c42)
        } else {
            const unsigned int b = mapa_u32(tile_base, 1u);
            TAPV(ld4_cluster(b + x  * 16), cbE, e40, e41, e42)
            TAPV(ld4_cluster(b + xm * 16), cbC, c40, c41, c42)
            TAPV(ld4_cluster(b + xp * 16), cbC, c40, c41, c42)
        }
        #undef TAPV

        const float inv_den = rcpf(bden);
        const float cen[3]  = { C.x, C.y, C.z };
        const float bnum[3] = { bn0, bn1, bn2 };
        const float gr[3]   = { fmaf(ef, e40, fmaf(ef2, c40, C.x)),
                                fmaf(ef, e41, fmaf(ef2, c41, C.y)),
                                fmaf(ef, e42, fmaf(ef2, c42, C.z)) };
        const int obase = ((row0 + ly) * HW + x) * 3;
        #pragma unroll
        for (int c = 0; c < CH; ++c) {
            const float bf     = bnum[c] * inv_den;
            const float detail = fmaf(-ifn2, gr[c], cen[c]);
            const float ad     = fabsf(detail);
            const float denom  = fmaxf(cen[c] + offset, 1e-5f);
            const float ne     = fminf(ad * gain * rcpf(denom), 10.0f);
            sum_noise += ne;
            sum_det   += ad;
            const float em    = ex2f(-(ne * ne) * invtau2L2);
            const float t1    = 1.0f - em;
            const float nmask = t1 * t1;
            const float dmask = fmaf(0.5f, tanhf_approx(khalf * (ad - 0.002f)), 0.5f);
            const float v     = fmaf(lam * detail, nmask * dmask, bf);
            dst[obase + c] = fminf(fmaxf(v, 1e-5f), 1.0f);
        }
    }

    // ---- CTA reduction of partial sums ----
    #pragma unroll
    for (int o = 16; o > 0; o >>= 1) {
        sum_noise += __shfl_xor_sync(0xFFFFFFFFu, sum_noise, o);
        sum_det   += __shfl_xor_sync(0xFFFFFFFFu, sum_det, o);
    }
    if ((tid & 31) == 0) {
        red[tid >> 5]       = sum_noise;          // 8 warps
        red[8 + (tid >> 5)] = sum_det;
    }
    __syncthreads();

    if (tid == 0) {
        float tn = 0.f, td = 0.f;
        #pragma unroll
        for (int w = 0; w < T_A / 32; ++w) { tn += red[w]; td += red[8 + w]; }
        red[16] = tn;  red[17] = td;              // own totals
        const unsigned int l18 = smem_u32(&red[18]);
        st_peer_f32(l18,     rank ^ 1u, tn);
        st_peer_f32(l18 + 4, rank ^ 1u, td);
    }

    // cluster barrier: release own deposits, acquire peer's
    asm volatile("barrier.cluster.arrive.aligned;" ::: "memory");
    asm volatile("barrier.cluster.wait.aligned;"   ::: "memory");
    __syncthreads();   // red[16..19] visible to all threads in this CTA

    const float tot_n = red[16] + red[18];
    const float tot_d = red[17] + red[19];
    const float inv_n = 1.0f / (float)NELEM;
    const bool skip = (tot_n * inv_n < 1e-4f) || (tot_d * inv_n < 1e-4f);

    // ---- rare path: rewrite own half with clip(x) ----
    if (skip) {
        const float4* s4 = (const float4*)(base + row0 * (HW * CH));
        float*        d  = dst + row0 * (HW * CH);
        #pragma unroll
        for (int i = 0; i < (ROWS_C * HW * CH / 4) / T_A; ++i) {
            const float4 v = s4[tid + i * T_A];
            const float w[4] = { v.x, v.y, v.z, v.w };
            const int wb = (tid + i * T_A) * 4;
            #pragma unroll
            for (int k = 0; k < 4; ++k)
                d[wb + k] = fminf(fmaxf(w[k], 1e-5f), 1.0f);
        }
    }
}

extern "C" void kernel_launch(void* const* d_in, const int* in_sizes, int n_in,
                              void* d_out, int out_size)
{
    const float* images = (const float*)d_in[0];
    const float* params = (const float*)d_in[1];
    const float* kptr   = (const float*)d_in[2];
    float*       out    = (float*)d_out;

    const int nimg = in_sizes[1] / 7;  // B*P = 512

    cudaFuncSetAttribute(dns_kernel,
                         cudaFuncAttributeMaxDynamicSharedMemorySize, SMEM_A);
    dns_kernel<<<nimg * 2, T_A, SMEM_A>>>(images, params, kptr, out);
}

// round 15
// speedup vs baseline: 1.0031x; 1.0031x over previous
#include <cuda_runtime.h>
#include <cstdint>

#define HW       64
#define CH       3
#define NPIX     (HW * HW)              // 4096
#define NELEM    (NPIX * CH)            // 12288 floats per image
#define ROWS_C   32                     // output rows per CTA (half image)
#define CPIX     (ROWS_C * HW)          // 2048 pixels per CTA
#define T_A      224                    // 7 warps
#define NWARP    (T_A / 32)             // 7
#define SMEM_A   (32 * 4 + CPIX * 16)   // scratch + 32-row tile = 32896 B
#define LOG2E    1.4426950408889634f

__device__ __forceinline__ float ex2f(float x) {
    float r; asm("ex2.approx.ftz.f32 %0, %1;" : "=f"(r) : "f"(x)); return r;
}
__device__ __forceinline__ float rcpf(float x) {
    float r; asm("rcp.approx.ftz.f32 %0, %1;" : "=f"(r) : "f"(x)); return r;
}
__device__ __forceinline__ float tanhf_approx(float x) {
    float r; asm("tanh.approx.f32 %0, %1;" : "=f"(r) : "f"(x)); return r;
}
__device__ __forceinline__ unsigned int smem_u32(const void* p) {
    unsigned int a;
    asm("{ .reg .u64 t; cvta.to.shared.u64 t, %1; cvt.u32.u64 %0, t; }"
        : "=r"(a) : "l"(p));
    return a;
}
__device__ __forceinline__ unsigned int mapa_u32(unsigned int a, unsigned int r) {
    unsigned int d;
    asm("mapa.shared::cluster.u32 %0, %1, %2;" : "=r"(d) : "r"(a), "r"(r));
    return d;
}
__device__ __forceinline__ float4 ld4_cluster(unsigned int a) {
    float4 v;
    asm volatile("ld.shared::cluster.v4.f32 {%0,%1,%2,%3}, [%4];"
                 : "=f"(v.x), "=f"(v.y), "=f"(v.z), "=f"(v.w) : "r"(a));
    return v;
}
__device__ __forceinline__ void st_peer_f32(unsigned int laddr, unsigned int peer_rank, float v) {
    unsigned int r;
    asm("mapa.shared::cluster.u32 %0, %1, %2;" : "=r"(r) : "r"(laddr), "r"(peer_rank));
    asm volatile("st.shared::cluster.f32 [%0], %1;" :: "r"(r), "f"(v) : "memory");
}

__global__ void __launch_bounds__(T_A, 7) __cluster_dims__(2, 1, 1)
dns_kernel(const float* __restrict__ images,
           const float* __restrict__ params,
           const float* __restrict__ kptr,
           float* __restrict__ out)
{
    extern __shared__ float smem[];
    // red layout: [0..6] noise warp partials, [8..14] det warp partials,
    //             [16..17] own totals, [18..19] peer totals
    float*  red  = smem;
    float*  buf  = smem + 32;            // CPIX float4 (own 32 rows only)
    float4* buf4 = (float4*)buf;

    const int tid = threadIdx.x;
    unsigned int rank;
    asm("mov.u32 %0, %%cluster_ctarank;" : "=r"(rank));

    const int img  = blockIdx.x >> 1;
    const int row0 = (int)rank * ROWS_C;          // first output row of CTA
    const float* base = images + (size_t)img * NELEM;
    float*       dst  = out    + (size_t)img * NELEM;

    // ---- stage own 32 rows: per-pixel gather + fused norm, one STS.128 ----
    {
        const float* src = base + row0 * (HW * CH);
        #pragma unroll
        for (int it = 0; it < (CPIX + T_A - 1) / T_A; ++it) {
            const int pp = tid + it * T_A;        // 0..2047 local pixel
            if (pp < CPIX) {
                const float* q = src + pp * 3;
                const float vx = q[0], vy = q[1], vz = q[2];
                const float nw = fmaf(vx, vx, fmaf(vy, vy, vz * vz));
                buf4[pp] = make_float4(vx, vy, vz, nw);
            }
        }
    }

    // ---- per-image parameters (uniform; L2-resident) ----
    const float* p = params + img * 7;
    const float sigma_s = fminf(fmaxf(p[0], 0.2f), 5.0f);
    const float sigma_r = fminf(fmaxf(p[1], 0.01f), 1.0f);
    const float sigma_f = fminf(fmaxf(p[2], 0.2f), 3.0f);
    const float lam     = fminf(fmaxf(p[3], 0.1f), 2.0f);
    const float tau     = fminf(fmaxf(p[4], 0.5f), 5.0f);
    const float gain    = fminf(fmaxf(p[5], 0.2f), 2.0f);
    const float offset  = fminf(fmaxf(p[6], 0.01f), 1.0f);
    const float k_pos   = fmaxf(fabsf(*kptr), 1.0f);

    const float ls2      = (-0.5f / (sigma_s * sigma_s)) * LOG2E;
    const float b_edge   = ls2;
    const float b_corner = 2.0f * ls2;
    const float cR       = (-0.5f / (sigma_r * sigma_r)) * LOG2E;
    const float m2       = -2.0f * cR;

    const float ef   = __expf(-0.5f / (sigma_f * sigma_f));
    const float ef2  = ef * ef;
    const float ifn  = rcpf(1.0f + 2.0f * ef);
    const float ifn2 = ifn * ifn;

    const float invtau2L2 = rcpf(tau * tau) * LOG2E;
    const float khalf     = 0.5f * k_pos;

    const unsigned int tile_base = smem_u32(buf);

    // both CTAs' tiles staged before cross-CTA halo reads
    __syncthreads();
    asm volatile("barrier.cluster.arrive.aligned;" ::: "memory");
    asm volatile("barrier.cluster.wait.aligned;"   ::: "memory");

    float sum_noise = 0.0f, sum_det = 0.0f;

    #pragma unroll
    for (int i = 0; i < (CPIX + T_A - 1) / T_A; ++i) {
        const int lp = tid + i * T_A;             // local pixel
        if (lp >= CPIX) break;                    // only last iteration partial
        const int ly = lp >> 6, x = lp & 63;      // ly warp-uniform (224%64==32)
        const int xm = abs(x - 1);
        const int xp = 63 - abs(62 - x);
        const int rC = ly * HW;

        const float4 C = buf4[rC + x];
        const float a0 = m2 * C.x, a1 = m2 * C.y, a2 = m2 * C.z;
        const float cbE = fmaf(cR, C.w, b_edge);
        const float cbC = fmaf(cR, C.w, b_corner);

        float bn0 = C.x, bn1 = C.y, bn2 = C.z, bden = 1.0f;
        float e40 = 0.f, e41 = 0.f, e42 = 0.f;
        float c40 = 0.f, c41 = 0.f, c42 = 0.f;

        #define TAPV(T, CB, A0, A1, A2)                                    \
        {                                                                  \
            const float4 t = (T);                                          \
            float arg = fmaf(cR, t.w, CB);                                 \
            arg = fmaf(a2, t.z, arg);                                      \
            arg = fmaf(a1, t.y, arg);                                      \
            arg = fmaf(a0, t.x, arg);                                      \
            const float kk = ex2f(arg);                                    \
            bden += kk;                                                    \
            bn0 = fmaf(kk, t.x, bn0);                                      \
            bn1 = fmaf(kk, t.y, bn1);                                      \
            bn2 = fmaf(kk, t.z, bn2);                                      \
            A0 += t.x; A1 += t.y; A2 += t.z;                               \
        }

        // center row (always local)
        TAPV(buf4[rC + xm], cbE, e40, e41, e42)
        TAPV(buf4[rC + xp], cbE, e40, e41, e42)

        // up row: remote only for rank1 at ly==0 (peer's row 31)
        if (!(ly == 0 && rank == 1)) {
            const int r = ((ly > 0) ? ly - 1 : 1) * HW;   // reflect for rank0
            TAPV(buf4[r + x ], cbE, e40, e41, e42)
            TAPV(buf4[r + xm], cbC, c40, c41, c42)
            TAPV(buf4[r + xp], cbC, c40, c41, c42)
        } else {
            const unsigned int b = mapa_u32(tile_base + 31u * (HW * 16), 0u);
            TAPV(ld4_cluster(b + x  * 16), cbE, e40, e41, e42)
            TAPV(ld4_cluster(b + xm * 16), cbC, c40, c41, c42)
            TAPV(ld4_cluster(b + xp * 16), cbC, c40, c41, c42)
        }

        // down row: remote only for rank0 at ly==31 (peer's row 0)
        if (!(ly == 31 && rank == 0)) {
            const int r = ((ly < 31) ? ly + 1 : 30) * HW; // reflect for rank1
            TAPV(buf4[r + x ], cbE, e40, e41, e42)
            TAPV(buf4[r + xm], cbC, c40, c41, c42)
            TAPV(buf4[r + xp], cbC, c40, c41, c42)
        } else {
            const unsigned int b = mapa_u32(tile_base, 1u);
            TAPV(ld4_cluster(b + x  * 16), cbE, e40, e41, e42)
            TAPV(ld4_cluster(b + xm * 16), cbC, c40, c41, c42)
            TAPV(ld4_cluster(b + xp * 16), cbC, c40, c41, c42)
        }
        #undef TAPV

        const float inv_den = rcpf(bden);
        const float cen[3]  = { C.x, C.y, C.z };
        const float bnum[3] = { bn0, bn1, bn2 };
        const float gr[3]   = { fmaf(ef, e40, fmaf(ef2, c40, C.x)),
                                fmaf(ef, e41, fmaf(ef2, c41, C.y)),
                                fmaf(ef, e42, fmaf(ef2, c42, C.z)) };
        const int obase = ((row0 + ly) * HW + x) * 3;
        #pragma unroll
        for (int c = 0; c < CH; ++c) {
            const float bf     = bnum[c] * inv_den;
            const float detail = fmaf(-ifn2, gr[c], cen[c]);
            const float ad     = fabsf(detail);
            const float denom  = fmaxf(cen[c] + offset, 1e-5f);
            const float ne     = fminf(ad * gain * rcpf(denom), 10.0f);
            sum_noise += ne;
            sum_det   += ad;
            const float em    = ex2f(-(ne * ne) * invtau2L2);
            const float t1    = 1.0f - em;
            const float nmask = t1 * t1;
            const float dmask = fmaf(0.5f, tanhf_approx(khalf * (ad - 0.002f)), 0.5f);
            const float v     = fmaf(lam * detail, nmask * dmask, bf);
            dst[obase + c] = fminf(fmaxf(v, 1e-5f), 1.0f);
        }
    }

    // ---- CTA reduction of partial sums ----
    #pragma unroll
    for (int o = 16; o > 0; o >>= 1) {
        sum_noise += __shfl_xor_sync(0xFFFFFFFFu, sum_noise, o);
        sum_det   += __shfl_xor_sync(0xFFFFFFFFu, sum_det, o);
    }
    if ((tid & 31) == 0) {
        red[tid >> 5]       = sum_noise;          // 7 warps
        red[8 + (tid >> 5)] = sum_det;
    }
    __syncthreads();

    if (tid == 0) {
        float tn = 0.f, td = 0.f;
        #pragma unroll
        for (int w = 0; w < NWARP; ++w) { tn += red[w]; td += red[8 + w]; }
        red[16] = tn;  red[17] = td;              // own totals
        const unsigned int l18 = smem_u32(&red[18]);
        st_peer_f32(l18,     rank ^ 1u, tn);
        st_peer_f32(l18 + 4, rank ^ 1u, td);
    }

    // cluster barrier: release own deposits, acquire peer's
    asm volatile("barrier.cluster.arrive.aligned;" ::: "memory");
    asm volatile("barrier.cluster.wait.aligned;"   ::: "memory");
    __syncthreads();   // red[16..19] visible to all threads in this CTA

    const float tot_n = red[16] + red[18];
    const float tot_d = red[17] + red[19];
    const float inv_n = 1.0f / (float)NELEM;
    const bool skip = (tot_n * inv_n < 1e-4f) || (tot_d * inv_n < 1e-4f);

    // ---- rare path: rewrite own half with clip(x) ----
    if (skip) {
        const float4* s4 = (const float4*)(base + row0 * (HW * CH));
        float*        d  = dst + row0 * (HW * CH);
        #pragma unroll
        for (int i = 0; i < (CPIX * 12 / 16 + T_A - 1) / T_A; ++i) {
            const int w4 = tid + i * T_A;         // 0..1535 float4 words
            if (w4 < CPIX * 12 / 16) {
                const float4 v = s4[w4];
                const float w[4] = { v.x, v.y, v.z, v.w };
                const int wb = w4 * 4;
                #pragma unroll
                for (int k = 0; k < 4; ++k)
                    d[wb + k] = fminf(fmaxf(w[k], 1e-5f), 1.0f);
            }
        }
    }
}

extern "C" void kernel_launch(void* const* d_in, const int* in_sizes, int n_in,
                              void* d_out, int out_size)
{
    const float* images = (const float*)d_in[0];
    const float* params = (const float*)d_in[1];
    const float* kptr   = (const float*)d_in[2];
    float*       out    = (float*)d_out;

    const int nimg = in_sizes[1] / 7;  // B*P = 512

    cudaFuncSetAttribute(dns_kernel,
                         cudaFuncAttributeMaxDynamicSharedMemorySize, SMEM_A);
    dns_kernel<<<nimg * 2, T_A, SMEM_A>>>(images, params, kptr, out);
}

// round 16
// speedup vs baseline: 1.0902x; 1.0869x over previous
#include <cuda_runtime.h>
#include <cstdint>

#define HW       64
#define CH       3
#define NPIX     (HW * HW)              // 4096
#define NELEM    (NPIX * CH)            // 12288 floats per image
#define ROWS_C   32                     // output rows per CTA (half image)
#define CPIX     (ROWS_C * HW)          // 2048 pixels per CTA
#define T_A      192                    // 6 warps
#define NWARP    (T_A / 32)             // 6
#define SMEM_A   (32 * 4 + CPIX * 16)   // scratch + 32-row tile = 32896 B
#define LOG2E    1.4426950408889634f

__device__ __forceinline__ float ex2f(float x) {
    float r; asm("ex2.approx.ftz.f32 %0, %1;" : "=f"(r) : "f"(x)); return r;
}
__device__ __forceinline__ float rcpf(float x) {
    float r; asm("rcp.approx.ftz.f32 %0, %1;" : "=f"(r) : "f"(x)); return r;
}
__device__ __forceinline__ float tanhf_approx(float x) {
    float r; asm("tanh.approx.f32 %0, %1;" : "=f"(r) : "f"(x)); return r;
}
__device__ __forceinline__ unsigned int smem_u32(const void* p) {
    unsigned int a;
    asm("{ .reg .u64 t; cvta.to.shared.u64 t, %1; cvt.u32.u64 %0, t; }"
        : "=r"(a) : "l"(p));
    return a;
}
__device__ __forceinline__ unsigned int mapa_u32(unsigned int a, unsigned int r) {
    unsigned int d;
    asm("mapa.shared::cluster.u32 %0, %1, %2;" : "=r"(d) : "r"(a), "r"(r));
    return d;
}
__device__ __forceinline__ float4 ld4_cluster(unsigned int a) {
    float4 v;
    asm volatile("ld.shared::cluster.v4.f32 {%0,%1,%2,%3}, [%4];"
                 : "=f"(v.x), "=f"(v.y), "=f"(v.z), "=f"(v.w) : "r"(a));
    return v;
}
__device__ __forceinline__ void st_peer_f32(unsigned int laddr, unsigned int peer_rank, float v) {
    unsigned int r;
    asm("mapa.shared::cluster.u32 %0, %1, %2;" : "=r"(r) : "r"(laddr), "r"(peer_rank));
    asm volatile("st.shared::cluster.f32 [%0], %1;" :: "r"(r), "f"(v) : "memory");
}

__global__ void __launch_bounds__(T_A, 7) __cluster_dims__(2, 1, 1)
dns_kernel(const float* __restrict__ images,
           const float* __restrict__ params,
           const float* __restrict__ kptr,
           float* __restrict__ out)
{
    extern __shared__ float smem[];
    // red layout: [0..5] noise warp partials, [8..13] det warp partials,
    //             [16..17] own totals, [18..19] peer totals
    float*  red  = smem;
    float*  buf  = smem + 32;            // CPIX float4 (own 32 rows only)
    float4* buf4 = (float4*)buf;

    const int tid = threadIdx.x;
    unsigned int rank;
    asm("mov.u32 %0, %%cluster_ctarank;" : "=r"(rank));

    const int img  = blockIdx.x >> 1;
    const int row0 = (int)rank * ROWS_C;          // first output row of CTA
    const float* base = images + (size_t)img * NELEM;
    float*       dst  = out    + (size_t)img * NELEM;

    // ---- stage own 32 rows: per-pixel gather + fused norm, one STS.128 ----
    {
        const float* src = base + row0 * (HW * CH);
        #pragma unroll
        for (int it = 0; it < (CPIX + T_A - 1) / T_A; ++it) {
            const int pp = tid + it * T_A;        // 0..2047 local pixel
            if (pp < CPIX) {
                const float* q = src + pp * 3;
                const float vx = q[0], vy = q[1], vz = q[2];
                const float nw = fmaf(vx, vx, fmaf(vy, vy, vz * vz));
                buf4[pp] = make_float4(vx, vy, vz, nw);
            }
        }
    }

    // ---- per-image parameters (uniform; L2-resident) ----
    const float* p = params + img * 7;
    const float sigma_s = fminf(fmaxf(p[0], 0.2f), 5.0f);
    const float sigma_r = fminf(fmaxf(p[1], 0.01f), 1.0f);
    const float sigma_f = fminf(fmaxf(p[2], 0.2f), 3.0f);
    const float lam     = fminf(fmaxf(p[3], 0.1f), 2.0f);
    const float tau     = fminf(fmaxf(p[4], 0.5f), 5.0f);
    const float gain    = fminf(fmaxf(p[5], 0.2f), 2.0f);
    const float offset  = fminf(fmaxf(p[6], 0.01f), 1.0f);
    const float k_pos   = fmaxf(fabsf(*kptr), 1.0f);

    const float ls2      = (-0.5f / (sigma_s * sigma_s)) * LOG2E;
    const float b_edge   = ls2;
    const float b_corner = 2.0f * ls2;
    const float cR       = (-0.5f / (sigma_r * sigma_r)) * LOG2E;
    const float m2       = -2.0f * cR;

    const float ef   = __expf(-0.5f / (sigma_f * sigma_f));
    const float ef2  = ef * ef;
    const float ifn  = rcpf(1.0f + 2.0f * ef);
    const float ifn2 = ifn * ifn;

    const float invtau2L2 = rcpf(tau * tau) * LOG2E;
    const float khalf     = 0.5f * k_pos;

    const unsigned int tile_base = smem_u32(buf);

    // both CTAs' tiles staged before cross-CTA halo reads
    __syncthreads();
    asm volatile("barrier.cluster.arrive.aligned;" ::: "memory");
    asm volatile("barrier.cluster.wait.aligned;"   ::: "memory");

    float sum_noise = 0.0f, sum_det = 0.0f;

    #pragma unroll
    for (int i = 0; i < (CPIX + T_A - 1) / T_A; ++i) {
        const int lp = tid + i * T_A;             // local pixel
        if (lp >= CPIX) break;                    // only last iteration partial
        const int ly = lp >> 6, x = lp & 63;      // ly warp-uniform (192%64==0)
        const int xm = abs(x - 1);
        const int xp = 63 - abs(62 - x);
        const int rC = ly * HW;

        const float4 C = buf4[rC + x];
        const float a0 = m2 * C.x, a1 = m2 * C.y, a2 = m2 * C.z;
        const float cbE = fmaf(cR, C.w, b_edge);
        const float cbC = fmaf(cR, C.w, b_corner);

        float bn0 = C.x, bn1 = C.y, bn2 = C.z, bden = 1.0f;
        float e40 = 0.f, e41 = 0.f, e42 = 0.f;
        float c40 = 0.f, c41 = 0.f, c42 = 0.f;

        #define TAPV(T, CB, A0, A1, A2)                                    \
        {                                                                  \
            const float4 t = (T);                                          \
            float arg = fmaf(cR, t.w, CB);                                 \
            arg = fmaf(a2, t.z, arg);                                      \
            arg = fmaf(a1, t.y, arg);                                      \
            arg = fmaf(a0, t.x, arg);                                      \
            const float kk = ex2f(arg);                                    \
            bden += kk;                                                    \
            bn0 = fmaf(kk, t.x, bn0);                                      \
            bn1 = fmaf(kk, t.y, bn1);                                      \
            bn2 = fmaf(kk, t.z, bn2);                                      \
            A0 += t.x; A1 += t.y; A2 += t.z;                               \
        }

        // center row (always local)
        TAPV(buf4[rC + xm], cbE, e40, e41, e42)
        TAPV(buf4[rC + xp], cbE, e40, e41, e42)

        // up row: remote only for rank1 at ly==0 (peer's row 31)
        if (!(ly == 0 && rank == 1)) {
            const int r = ((ly > 0) ? ly - 1 : 1) * HW;   // reflect for rank0
            TAPV(buf4[r + x ], cbE, e40, e41, e42)
            TAPV(buf4[r + xm], cbC, c40, c41, c42)
            TAPV(buf4[r + xp], cbC, c40, c41, c42)
        } else {
            const unsigned int b = mapa_u32(tile_base + 31u * (HW * 16), 0u);
            TAPV(ld4_cluster(b + x  * 16), cbE, e40, e41, e42)
            TAPV(ld4_cluster(b + xm * 16), cbC, c40, c41, c42)
            TAPV(ld4_cluster(b + xp * 16), cbC, c40, c41, c42)
        }

        // down row: remote only for rank0 at ly==31 (peer's row 0)
        if (!(ly == 31 && rank == 0)) {
            const int r = ((ly < 31) ? ly + 1 : 30) * HW; // reflect for rank1
            TAPV(buf4[r + x ], cbE, e40, e41, e42)
            TAPV(buf4[r + xm], cbC, c40, c41, c42)
            TAPV(buf4[r + xp], cbC, c40, c41, c42)
        } else {
            const unsigned int b = mapa_u32(tile_base, 1u);
            TAPV(ld4_cluster(b + x  * 16), cbE, e40, e41, e42)
            TAPV(ld4_cluster(b + xm * 16), cbC, c40, c41, c42)
            TAPV(ld4_cluster(b + xp * 16), cbC, c40, c41, c42)
        }
        #undef TAPV

        const float inv_den = rcpf(bden);
        const float cen[3]  = { C.x, C.y, C.z };
        const float bnum[3] = { bn0, bn1, bn2 };
        const float gr[3]   = { fmaf(ef, e40, fmaf(ef2, c40, C.x)),
                                fmaf(ef, e41, fmaf(ef2, c41, C.y)),
                                fmaf(ef, e42, fmaf(ef2, c42, C.z)) };
        const int obase = ((row0 + ly) * HW + x) * 3;
        #pragma unroll
        for (int c = 0; c < CH; ++c) {
            const float bf     = bnum[c] * inv_den;
            const float detail = fmaf(-ifn2, gr[c], cen[c]);
            const float ad     = fabsf(detail);
            const float denom  = fmaxf(cen[c] + offset, 1e-5f);
            const float ne     = fminf(ad * gain * rcpf(denom), 10.0f);
            sum_noise += ne;
            sum_det   += ad;
            const float em    = ex2f(-(ne * ne) * invtau2L2);
            const float t1    = 1.0f - em;
            const float nmask = t1 * t1;
            const float dmask = fmaf(0.5f, tanhf_approx(khalf * (ad - 0.002f)), 0.5f);
            const float v     = fmaf(lam * detail, nmask * dmask, bf);
            dst[obase + c] = fminf(fmaxf(v, 1e-5f), 1.0f);
        }
    }

    // ---- CTA reduction of partial sums ----
    #pragma unroll
    for (int o = 16; o > 0; o >>= 1) {
        sum_noise += __shfl_xor_sync(0xFFFFFFFFu, sum_noise, o);
        sum_det   += __shfl_xor_sync(0xFFFFFFFFu, sum_det, o);
    }
    if ((tid & 31) == 0) {
        red[tid >> 5]       = sum_noise;          // 6 warps
        red[8 + (tid >> 5)] = sum_det;
    }
    __syncthreads();

    if (tid == 0) {
        float tn = 0.f, td = 0.f;
        #pragma unroll
        for (int w = 0; w < NWARP; ++w) { tn += red[w]; td += red[8 + w]; }
        red[16] = tn;  red[17] = td;              // own totals
        const unsigned int l18 = smem_u32(&red[18]);
        st_peer_f32(l18,     rank ^ 1u, tn);
        st_peer_f32(l18 + 4, rank ^ 1u, td);
    }

    // cluster barrier: release own deposits, acquire peer's
    asm volatile("barrier.cluster.arrive.aligned;" ::: "memory");
    asm volatile("barrier.cluster.wait.aligned;"   ::: "memory");
    __syncthreads();   // red[16..19] visible to all threads in this CTA

    const float tot_n = red[16] + red[18];
    const float tot_d = red[17] + red[19];
    const float inv_n = 1.0f / (float)NELEM;
    const bool skip = (tot_n * inv_n < 1e-4f) || (tot_d * inv_n < 1e-4f);

    // ---- rare path: rewrite own half with clip(x) ----
    if (skip) {
        const float4* s4 = (const float4*)(base + row0 * (HW * CH));
        float*        d  = dst + row0 * (HW * CH);
        #pragma unroll
        for (int i = 0; i < (CPIX * 12 / 16 + T_A - 1) / T_A; ++i) {
            const int w4 = tid + i * T_A;         // 0..1535 float4 words
            if (w4 < CPIX * 12 / 16) {
                const float4 v = s4[w4];
                const float w[4] = { v.x, v.y, v.z, v.w };
                const int wb = w4 * 4;
                #pragma unroll
                for (int k = 0; k < 4; ++k)
                    d[wb + k] = fminf(fmaxf(w[k], 1e-5f), 1.0f);
            }
        }
    }
}

extern "C" void kernel_launch(void* const* d_in, const int* in_sizes, int n_in,
                              void* d_out, int out_size)
{
    const float* images = (const float*)d_in[0];
    const float* params = (const float*)d_in[1];
    const float* kptr   = (const float*)d_in[2];
    float*       out    = (float*)d_out;

    const int nimg = in_sizes[1] / 7;  // B*P = 512

    cudaFuncSetAttribute(dns_kernel,
                         cudaFuncAttributeMaxDynamicSharedMemorySize, SMEM_A);
    dns_kernel<<<nimg * 2, T_A, SMEM_A>>>(images, params, kptr, out);
}

// round 17
// speedup vs baseline: 1.1545x; 1.0590x over previous
#include <cuda_runtime.h>
#include <cstdint>

#define HW       64
#define CH       3
#define NPIX     (HW * HW)              // 4096
#define NELEM    (NPIX * CH)            // 12288 floats per image
#define CLUST    4                      // CTAs per image
#define ROWS_C   (HW / CLUST)           // 16 output rows per CTA
#define CPIX     (ROWS_C * HW)          // 1024 pixels per CTA
#define T_A      128                    // 4 warps
#define NWARP    (T_A / 32)             // 4
#define SMEM_A   (32 * 4 + CPIX * 16)   // scratch + tile = 16512 B
#define LOG2E    1.4426950408889634f

__device__ __forceinline__ float ex2f(float x) {
    float r; asm("ex2.approx.ftz.f32 %0, %1;" : "=f"(r) : "f"(x)); return r;
}
__device__ __forceinline__ float rcpf(float x) {
    float r; asm("rcp.approx.ftz.f32 %0, %1;" : "=f"(r) : "f"(x)); return r;
}
__device__ __forceinline__ float tanhf_approx(float x) {
    float r; asm("tanh.approx.f32 %0, %1;" : "=f"(r) : "f"(x)); return r;
}
__device__ __forceinline__ unsigned int smem_u32(const void* p) {
    unsigned int a;
    asm("{ .reg .u64 t; cvta.to.shared.u64 t, %1; cvt.u32.u64 %0, t; }"
        : "=r"(a) : "l"(p));
    return a;
}
__device__ __forceinline__ unsigned int mapa_u32(unsigned int a, unsigned int r) {
    unsigned int d;
    asm("mapa.shared::cluster.u32 %0, %1, %2;" : "=r"(d) : "r"(a), "r"(r));
    return d;
}
__device__ __forceinline__ float4 ld4_cluster(unsigned int a) {
    float4 v;
    asm volatile("ld.shared::cluster.v4.f32 {%0,%1,%2,%3}, [%4];"
                 : "=f"(v.x), "=f"(v.y), "=f"(v.z), "=f"(v.w) : "r"(a));
    return v;
}
__device__ __forceinline__ void st_peer_f32(unsigned int laddr, unsigned int peer_rank, float v) {
    unsigned int r;
    asm("mapa.shared::cluster.u32 %0, %1, %2;" : "=r"(r) : "r"(laddr), "r"(peer_rank));
    asm volatile("st.shared::cluster.f32 [%0], %1;" :: "r"(r), "f"(v) : "memory");
}

__global__ void __launch_bounds__(T_A, 12) __cluster_dims__(CLUST, 1, 1)
dns_kernel(const float* __restrict__ images,
           const float* __restrict__ params,
           const float* __restrict__ kptr,
           float* __restrict__ out)
{
    extern __shared__ float smem[];
    // red layout: [0..3] noise warp partials, [8..11] det warp partials,
    //             [16..19] per-rank noise totals, [20..23] per-rank det totals
    float*  red  = smem;
    float*  buf  = smem + 32;            // CPIX float4 (own 16 rows only)
    float4* buf4 = (float4*)buf;

    const int tid = threadIdx.x;
    unsigned int rank;
    asm("mov.u32 %0, %%cluster_ctarank;" : "=r"(rank));

    const int img  = blockIdx.x / CLUST;
    const int row0 = (int)rank * ROWS_C;          // first output row of CTA
    const float* base = images + (size_t)img * NELEM;
    float*       dst  = out    + (size_t)img * NELEM;

    // ---- stage own 16 rows: per-pixel gather + fused norm, one STS.128 ----
    {
        const float* src = base + row0 * (HW * CH);
        #pragma unroll
        for (int it = 0; it < CPIX / T_A; ++it) {
            const int pp = tid + it * T_A;        // 0..1023 local pixel
            const float* q = src + pp * 3;
            const float vx = q[0], vy = q[1], vz = q[2];
            const float nw = fmaf(vx, vx, fmaf(vy, vy, vz * vz));
            buf4[pp] = make_float4(vx, vy, vz, nw);
        }
    }

    // ---- per-image parameters (uniform; L2-resident) ----
    const float* p = params + img * 7;
    const float sigma_s = fminf(fmaxf(p[0], 0.2f), 5.0f);
    const float sigma_r = fminf(fmaxf(p[1], 0.01f), 1.0f);
    const float sigma_f = fminf(fmaxf(p[2], 0.2f), 3.0f);
    const float lam     = fminf(fmaxf(p[3], 0.1f), 2.0f);
    const float tau     = fminf(fmaxf(p[4], 0.5f), 5.0f);
    const float gain    = fminf(fmaxf(p[5], 0.2f), 2.0f);
    const float offset  = fminf(fmaxf(p[6], 0.01f), 1.0f);
    const float k_pos   = fmaxf(fabsf(*kptr), 1.0f);

    const float ls2      = (-0.5f / (sigma_s * sigma_s)) * LOG2E;
    const float b_edge   = ls2;
    const float b_corner = 2.0f * ls2;
    const float cR       = (-0.5f / (sigma_r * sigma_r)) * LOG2E;
    const float m2       = -2.0f * cR;

    const float ef   = __expf(-0.5f / (sigma_f * sigma_f));
    const float ef2  = ef * ef;
    const float ifn  = rcpf(1.0f + 2.0f * ef);
    const float ifn2 = ifn * ifn;

    const float invtau2L2 = rcpf(tau * tau) * LOG2E;
    const float khalf     = 0.5f * k_pos;

    const unsigned int tile_base = smem_u32(buf);

    // all 4 CTAs' tiles staged before cross-CTA halo reads
    __syncthreads();
    asm volatile("barrier.cluster.arrive.aligned;" ::: "memory");
    asm volatile("barrier.cluster.wait.aligned;"   ::: "memory");

    float sum_noise = 0.0f, sum_det = 0.0f;

    #pragma unroll
    for (int i = 0; i < CPIX / T_A; ++i) {
        const int lp = tid + i * T_A;             // local pixel
        const int ly = lp >> 6, x = lp & 63;      // ly warp-uniform
        const int xm = abs(x - 1);
        const int xp = 63 - abs(62 - x);
        const int rC = ly * HW;

        const float4 C = buf4[rC + x];
        const float a0 = m2 * C.x, a1 = m2 * C.y, a2 = m2 * C.z;
        const float cbE = fmaf(cR, C.w, b_edge);
        const float cbC = fmaf(cR, C.w, b_corner);

        float bn0 = C.x, bn1 = C.y, bn2 = C.z, bden = 1.0f;
        float e40 = 0.f, e41 = 0.f, e42 = 0.f;
        float c40 = 0.f, c41 = 0.f, c42 = 0.f;

        #define TAPV(T, CB, A0, A1, A2)                                    \
        {                                                                  \
            const float4 t = (T);                                          \
            float arg = fmaf(cR, t.w, CB);                                 \
            arg = fmaf(a2, t.z, arg);                                      \
            arg = fmaf(a1, t.y, arg);                                      \
            arg = fmaf(a0, t.x, arg);                                      \
            const float kk = ex2f(arg);                                    \
            bden += kk;                                                    \
            bn0 = fmaf(kk, t.x, bn0);                                      \
            bn1 = fmaf(kk, t.y, bn1);                                      \
            bn2 = fmaf(kk, t.z, bn2);                                      \
            A0 += t.x; A1 += t.y; A2 += t.z;                               \
        }

        // center row (always local)
        TAPV(buf4[rC + xm], cbE, e40, e41, e42)
        TAPV(buf4[rC + xp], cbE, e40, e41, e42)

        // up row: remote when ly==0 and not top CTA (peer rank-1 row 15)
        if (!(ly == 0 && rank != 0)) {
            const int r = ((ly > 0) ? ly - 1 : 1) * HW;    // reflect for rank0
            TAPV(buf4[r + x ], cbE, e40, e41, e42)
            TAPV(buf4[r + xm], cbC, c40, c41, c42)
            TAPV(buf4[r + xp], cbC, c40, c41, c42)
        } else {
            const unsigned int b =
                mapa_u32(tile_base + (ROWS_C - 1) * (HW * 16), rank - 1u);
            TAPV(ld4_cluster(b + x  * 16), cbE, e40, e41, e42)
            TAPV(ld4_cluster(b + xm * 16), cbC, c40, c41, c42)
            TAPV(ld4_cluster(b + xp * 16), cbC, c40, c41, c42)
        }

        // down row: remote when ly==15 and not bottom CTA (peer rank+1 row 0)
        if (!(ly == ROWS_C - 1 && rank != CLUST - 1)) {
            const int r = ((ly < ROWS_C - 1) ? ly + 1 : ROWS_C - 2) * HW;
            TAPV(buf4[r + x ], cbE, e40, e41, e42)
            TAPV(buf4[r + xm], cbC, c40, c41, c42)
            TAPV(buf4[r + xp], cbC, c40, c41, c42)
        } else {
            const unsigned int b = mapa_u32(tile_base, rank + 1u);
            TAPV(ld4_cluster(b + x  * 16), cbE, e40, e41, e42)
            TAPV(ld4_cluster(b + xm * 16), cbC, c40, c41, c42)
            TAPV(ld4_cluster(b + xp * 16), cbC, c40, c41, c42)
        }
        #undef TAPV

        const float inv_den = rcpf(bden);
        const float cen[3]  = { C.x, C.y, C.z };
        const float bnum[3] = { bn0, bn1, bn2 };
        const float gr[3]   = { fmaf(ef, e40, fmaf(ef2, c40, C.x)),
                                fmaf(ef, e41, fmaf(ef2, c41, C.y)),
                                fmaf(ef, e42, fmaf(ef2, c42, C.z)) };
        const int obase = ((row0 + ly) * HW + x) * 3;
        #pragma unroll
        for (int c = 0; c < CH; ++c) {
            const float bf     = bnum[c] * inv_den;
            const float detail = fmaf(-ifn2, gr[c], cen[c]);
            const float ad     = fabsf(detail);
            const float denom  = fmaxf(cen[c] + offset, 1e-5f);
            const float ne     = fminf(ad * gain * rcpf(denom), 10.0f);
            sum_noise += ne;
            sum_det   += ad;
            const float em    = ex2f(-(ne * ne) * invtau2L2);
            const float t1    = 1.0f - em;
            const float nmask = t1 * t1;
            const float dmask = fmaf(0.5f, tanhf_approx(khalf * (ad - 0.002f)), 0.5f);
            const float v     = fmaf(lam * detail, nmask * dmask, bf);
            dst[obase + c] = fminf(fmaxf(v, 1e-5f), 1.0f);
        }
    }

    // ---- CTA reduction of partial sums ----
    #pragma unroll
    for (int o = 16; o > 0; o >>= 1) {
        sum_noise += __shfl_xor_sync(0xFFFFFFFFu, sum_noise, o);
        sum_det   += __shfl_xor_sync(0xFFFFFFFFu, sum_det, o);
    }
    if ((tid & 31) == 0) {
        red[tid >> 5]       = sum_noise;          // 4 warps
        red[8 + (tid >> 5)] = sum_det;
    }
    __syncthreads();

    if (tid == 0) {
        float tn = 0.f, td = 0.f;
        #pragma unroll
        for (int w = 0; w < NWARP; ++w) { tn += red[w]; td += red[8 + w]; }
        // deposit own totals into slot [16+rank]/[20+rank] of ALL 4 CTAs
        const unsigned int ln = smem_u32(&red[16 + rank]);
        const unsigned int ld = smem_u32(&red[20 + rank]);
        #pragma unroll
        for (unsigned int r = 0; r < CLUST; ++r) {
            st_peer_f32(ln, r, tn);
            st_peer_f32(ld, r, td);
        }
    }

    // cluster barrier: release own deposits, acquire peers'
    asm volatile("barrier.cluster.arrive.aligned;" ::: "memory");
    asm volatile("barrier.cluster.wait.aligned;"   ::: "memory");
    __syncthreads();   // red[16..23] visible to all threads in this CTA

    const float tot_n = red[16] + red[17] + red[18] + red[19];
    const float tot_d = red[20] + red[21] + red[22] + red[23];
    const float inv_n = 1.0f / (float)NELEM;
    const bool skip = (tot_n * inv_n < 1e-4f) || (tot_d * inv_n < 1e-4f);

    // ---- rare path: rewrite own 16 rows with clip(x) ----
    if (skip) {
        const float4* s4 = (const float4*)(base + row0 * (HW * CH));
        float*        d  = dst + row0 * (HW * CH);
        #pragma unroll
        for (int i = 0; i < (CPIX * 12 / 16) / T_A; ++i) {
            const int w4 = tid + i * T_A;         // 0..767 float4 words
            const float4 v = s4[w4];
            const float w[4] = { v.x, v.y, v.z, v.w };
            const int wb = w4 * 4;
            #pragma unroll
            for (int k = 0; k < 4; ++k)
                d[wb + k] = fminf(fmaxf(w[k], 1e-5f), 1.0f);
        }
    }
}

extern "C" void kernel_launch(void* const* d_in, const int* in_sizes, int n_in,
                              void* d_out, int out_size)
{
    const float* images = (const float*)d_in[0];
    const float* params = (const float*)d_in[1];
    const float* kptr   = (const float*)d_in[2];
    float*       out    = (float*)d_out;

    const int nimg = in_sizes[1] / 7;  // B*P = 512

    cudaFuncSetAttribute(dns_kernel,
                         cudaFuncAttributeMaxDynamicSharedMemorySize, SMEM_A);
    dns_kernel<<<nimg * CLUST, T_A, SMEM_A>>>(images, params, kptr, out);
}